// round 10
// baseline (speedup 1.0000x reference)
#include <cuda_runtime.h>

// cumprod along dim 1 of a (4096, 8192) fp32 matrix.
// PERSISTENT CTAs (740 = 5/SM x 148) with dynamic row scheduling via a
// global atomic counter: phase stagger between CTAs develops once and
// persists (no wave-relaunch phase re-alignment), tail self-balances.
// Per-row algorithm = R8 winner: warp w owns floats [1024w,1024w+1024),
// lane L owns float4 L of each 128-float chunk (coalesced LDG/STG.128),
// values register-resident end-to-end, early order-independent segment
// totals, ONE barrier per row (wtot/snext parity double-buffered).

#define ROW_LEN  8192
#define NROWS    4096
#define THREADS  256
#define NWARPS   8
#define CHUNKS   8
#define SEG_VEC  256
#define GRID     740                  // 5 CTAs/SM * 148 SMs

__device__ int g_row_ctr;

__global__ void reset_ctr_kernel() { g_row_ctr = 0; }

__global__ void __launch_bounds__(THREADS, 5)
cumprod_dim1_kernel(const float* __restrict__ x, float* __restrict__ y) {
    __shared__ float wtot[2][NWARPS];
    __shared__ int   snext[2];

    const int t    = threadIdx.x;
    const int lane = t & 31;
    const int w    = t >> 5;
    const int segl = w * SEG_VEC + lane;   // float4 index of lane's slot, chunk 0

    if (t == 0) snext[0] = atomicAdd(&g_row_ctr, 1);
    __syncthreads();

    int p = 0;
    int r = snext[0];

    while (r < NROWS) {
        const size_t row_off = (size_t)r * ROW_LEN;
        const float4* __restrict__ xin  = reinterpret_cast<const float4*>(x + row_off);
        float4* __restrict__       yout = reinterpret_cast<float4*>(y + row_off);

        // ---- front-batched loads: 8 LDG.128 in flight per warp ----
        float4 vals[CHUNKS];
        #pragma unroll
        for (int c = 0; c < CHUNKS; c++)
            vals[c] = __ldcs(&xin[segl + c * 32]);

        // prefetch next row index while loads are in flight
        if (t == 0) snext[p ^ 1] = atomicAdd(&g_row_ctr, 1);

        // ---- EARLY segment total: order-independent tree product ----
        float tp = 1.0f;
        #pragma unroll
        for (int c = 0; c < CHUNKS; c++) {
            float4 v = vals[c];
            tp *= (v.x * v.y) * (v.z * v.w);
        }
        #pragma unroll
        for (int o = 1; o < 32; o <<= 1)
            tp *= __shfl_xor_sync(0xffffffffu, tp, o);
        if (lane == 0) wtot[p][w] = tp;
        __syncthreads();                 // covers wtot[p] and snext[p^1]

        const int rnext = snext[p ^ 1];

        // ---- cross-warp exclusive prefix, folded into the running carry ----
        float carry = 1.0f;
        #pragma unroll
        for (int ww = 0; ww < NWARPS - 1; ww++) {
            float wt = wtot[p][ww];
            if (ww < w) carry *= wt;
        }

        // ---- scan + scale + store, single pass ----
        #pragma unroll
        for (int c = 0; c < CHUNKS; c++) {
            float4 v = vals[c];
            v.y *= v.x;
            v.z *= v.y;
            v.w *= v.z;

            float s = v.w;
            #pragma unroll
            for (int o = 1; o < 32; o <<= 1) {
                float tv = __shfl_up_sync(0xffffffffu, s, o);
                if (lane >= o) s *= tv;
            }
            float e   = __shfl_up_sync(0xffffffffu, s, 1);
            if (lane == 0) e = 1.0f;
            float tot = __shfl_sync(0xffffffffu, s, 31);

            const float ce = carry * e;
            v.x *= ce; v.y *= ce; v.z *= ce; v.w *= ce;
            __stcs(&yout[segl + c * 32], v);

            carry *= tot;
        }

        r = rnext;
        p ^= 1;
    }
}

extern "C" void kernel_launch(void* const* d_in, const int* in_sizes, int n_in,
                              void* d_out, int out_size) {
    const float* x = (const float*)d_in[0];
    float* y = (float*)d_out;
    reset_ctr_kernel<<<1, 1>>>();
    cumprod_dim1_kernel<<<GRID, THREADS>>>(x, y);
}